// round 8
// baseline (speedup 1.0000x reference)
#include <cuda_runtime.h>
#include <math.h>

#define Bsz   32
#define Tlen  2048
#define Hdim  512
#define Gdim  2048
#define HB    (Hdim*Bsz)      // 16384
#define NBS   32              // blocks per GEMM stage
#define NBA0  4               // embedding gather blocks
#define RPB   64              // gate rows per block
#define UPB   16              // hidden units per recurrent block
#define LAG   64              // run-ahead throttle (keeps traffic in L2)
#define THR   512
#define GPAD  34              // gate-exchange row stride
#define PPAD  33              // partial-buffer row stride
#define PSTR  (RPB*PPAD)      // 2112 floats per kh-partial plane

// smem layout (floats) — no input staging buffer anymore
#define SM_W    (Hdim*RPB)            // 32768 (k-pair interleaved)
#define SM_PART (3*PSTR)              // 6336
#define SM_GATE (RPB*GPAD)            // 2176
#define SMEM_FLOATS (SM_W+SM_PART+SM_GATE)   // 41280
#define SMEM_BYTES  (SMEM_FLOATS*4)          // 165120

// ---------------- global scratch ------------------------------------------
static __device__ __align__(16) float g_embT[(size_t)Tlen*HB];
static __device__ __align__(16) float g_ix1[(size_t)Tlen*Gdim*Bsz];
static __device__ __align__(16) float g_ix2[(size_t)Tlen*Gdim*Bsz];
static __device__ __align__(16) float g_h1[(size_t)(Tlen+1)*HB];
static __device__ __align__(16) float g_h2[(size_t)(Tlen+1)*HB];
static __device__ int g_f_embT[Tlen];
static __device__ int g_f_ix1[Tlen];
static __device__ int g_f_ix2[Tlen];
static __device__ int g_f_h1[Tlen+1];
static __device__ int g_f_h2[Tlen+1];

// ---------------- helpers --------------------------------------------------
union U64F2 { unsigned long long u; float2 f; };

__device__ __forceinline__ float sigf(float x) { return 1.0f / (1.0f + expf(-x)); }

// warp-wide acquire spin: all lanes poll same address (1 sector req/poll)
__device__ __forceinline__ void spin_acq(const int* p, int v) {
    int x;
    for (;;) {
        asm volatile("ld.acquire.gpu.global.s32 %0, [%1];" : "=r"(x) : "l"(p) : "memory");
        if (x >= v) break;
        __nanosleep(50);
    }
}

// Stage W slice [64 rows x 512 k] into smem, k-PAIR interleaved so the inner
// loop fetches rows {lane, lane+32} for k and k+1 with a single LDS.128:
//   Wsm[(k>>1)*128 + (r&31)*4 + (k&1)*2 + (r>>5)]
__device__ __forceinline__ void load_W(float* Wsm, const float* __restrict__ Wg,
                                       int rowbase, bool strided, int j, int tid) {
    for (int idx = tid; idx < RPB*Hdim; idx += THR) {
        int rl = idx >> 9, k = idx & 511;
        int grow = strided ? ((rl >> 4)*Hdim + j*UPB + (rl & 15)) : (rowbase + rl);
        Wsm[(k >> 1)*128 + (rl & 31)*4 + (k & 1)*2 + (rl >> 5)] =
            Wg[(size_t)grow*Hdim + k];
    }
}

// Split-K GEMM, input read DIRECTLY from global (L2) via broadcast ldcg.
// Thread (lane,q,kh): rows {lane, lane+32}, batches q*8..q*8+7, k in
// [kh*128, kh*128+128). 64 k-pair iterations, 16 FMA2 each.
__device__ __forceinline__ void gemm2(const float* __restrict__ Wsm,
                                      const float* __restrict__ gin,
                                      int lane, int q, int kh,
                                      unsigned long long acc[8]) {
#pragma unroll
    for (int i = 0; i < 8; ++i) acc[i] = 0ull;
    const float4* wp = reinterpret_cast<const float4*>(Wsm) + kh*2048 + lane;
    const float* ib = gin + kh*128*Bsz + q*8;
#pragma unroll 4
    for (int p = 0; p < 64; ++p) {
        float4 w = wp[p*32];
        const ulonglong2* i0 = reinterpret_cast<const ulonglong2*>(ib + p*64);
        ulonglong2 v00 = __ldcg(i0);
        ulonglong2 v01 = __ldcg(reinterpret_cast<const ulonglong2*>(ib + p*64 + 4));
        ulonglong2 v10 = __ldcg(reinterpret_cast<const ulonglong2*>(ib + p*64 + 32));
        ulonglong2 v11 = __ldcg(reinterpret_cast<const ulonglong2*>(ib + p*64 + 36));
        unsigned long long wa, wb, wc, wd;
        asm("mov.b64 %0, {%1, %1};" : "=l"(wa) : "f"(w.x));
        asm("mov.b64 %0, {%1, %1};" : "=l"(wb) : "f"(w.y));
        asm("mov.b64 %0, {%1, %1};" : "=l"(wc) : "f"(w.z));
        asm("mov.b64 %0, {%1, %1};" : "=l"(wd) : "f"(w.w));
        asm("fma.rn.f32x2 %0, %1, %2, %0;" : "+l"(acc[0]) : "l"(wa), "l"(v00.x));
        asm("fma.rn.f32x2 %0, %1, %2, %0;" : "+l"(acc[1]) : "l"(wa), "l"(v00.y));
        asm("fma.rn.f32x2 %0, %1, %2, %0;" : "+l"(acc[2]) : "l"(wa), "l"(v01.x));
        asm("fma.rn.f32x2 %0, %1, %2, %0;" : "+l"(acc[3]) : "l"(wa), "l"(v01.y));
        asm("fma.rn.f32x2 %0, %1, %2, %0;" : "+l"(acc[4]) : "l"(wb), "l"(v00.x));
        asm("fma.rn.f32x2 %0, %1, %2, %0;" : "+l"(acc[5]) : "l"(wb), "l"(v00.y));
        asm("fma.rn.f32x2 %0, %1, %2, %0;" : "+l"(acc[6]) : "l"(wb), "l"(v01.x));
        asm("fma.rn.f32x2 %0, %1, %2, %0;" : "+l"(acc[7]) : "l"(wb), "l"(v01.y));
        asm("fma.rn.f32x2 %0, %1, %2, %0;" : "+l"(acc[0]) : "l"(wc), "l"(v10.x));
        asm("fma.rn.f32x2 %0, %1, %2, %0;" : "+l"(acc[1]) : "l"(wc), "l"(v10.y));
        asm("fma.rn.f32x2 %0, %1, %2, %0;" : "+l"(acc[2]) : "l"(wc), "l"(v11.x));
        asm("fma.rn.f32x2 %0, %1, %2, %0;" : "+l"(acc[3]) : "l"(wc), "l"(v11.y));
        asm("fma.rn.f32x2 %0, %1, %2, %0;" : "+l"(acc[4]) : "l"(wd), "l"(v10.x));
        asm("fma.rn.f32x2 %0, %1, %2, %0;" : "+l"(acc[5]) : "l"(wd), "l"(v10.y));
        asm("fma.rn.f32x2 %0, %1, %2, %0;" : "+l"(acc[6]) : "l"(wd), "l"(v11.x));
        asm("fma.rn.f32x2 %0, %1, %2, %0;" : "+l"(acc[7]) : "l"(wd), "l"(v11.y));
    }
}

__device__ __forceinline__ void write_partials(float* part, int kh, int lane, int q,
                                               const unsigned long long acc[8]) {
#pragma unroll
    for (int rr = 0; rr < 2; ++rr) {
        float* pp = part + (kh-1)*PSTR + (lane + rr*32)*PPAD + q*8;
#pragma unroll
        for (int m = 0; m < 4; ++m) {
            U64F2 u; u.u = acc[rr*4 + m];
            pp[2*m] = u.f.x; pp[2*m + 1] = u.f.y;
        }
    }
}

// ---------------- pipeline stages -----------------------------------------
__device__ void stage_ff(int j, int tid, float* Wsm, float* part,
                         const float* Wg, const float* biasA, const float* biasB,
                         const float* inbase, int slot_off, int* f_in, int in_thresh,
                         float* outbase, int* f_out, int* f_throttle) {
    load_W(Wsm, Wg, j*RPB, false, j, tid);
    int lane = tid & 31, w = tid >> 5, q = w & 3, kh = w >> 2;
    float bias0 = biasA[j*RPB + lane]      + biasB[j*RPB + lane];
    float bias1 = biasA[j*RPB + lane + 32] + biasB[j*RPB + lane + 32];
    __syncthreads();
    for (int t = 0; t < Tlen; ++t) {
        spin_acq(&f_in[t + slot_off], in_thresh);
        if (t >= LAG) spin_acq(&f_throttle[t - LAG], NBS);
        unsigned long long acc[8];
        gemm2(Wsm, inbase + (size_t)(t + slot_off)*HB, lane, q, kh, acc);
        if (kh > 0) write_partials(part, kh, lane, q, acc);
        __syncthreads();
        if (kh == 0) {
#pragma unroll
            for (int rr = 0; rr < 2; ++rr) {
                int r = lane + rr*32;
                float bias = rr ? bias1 : bias0;
                const float* pp = part + r*PPAD + q*8;
                float2* op = reinterpret_cast<float2*>(
                    outbase + ((size_t)t*Gdim + j*RPB + r)*Bsz + q*8);
#pragma unroll
                for (int m = 0; m < 4; ++m) {
                    U64F2 u; u.u = acc[rr*4 + m];
                    float2 g;
                    g.x = u.f.x + pp[2*m]   + pp[PSTR + 2*m]   + pp[2*PSTR + 2*m]   + bias;
                    g.y = u.f.y + pp[2*m+1] + pp[PSTR + 2*m+1] + pp[2*PSTR + 2*m+1] + bias;
                    op[m] = g;
                }
            }
            __threadfence();
        }
        __syncthreads();
        if (tid == 0) atomicAdd(&f_out[t], 1);
    }
}

__device__ void stage_rec(int j, int tid, float* Wsm, float* part, float* gsm,
                          const float* Wg, const float* ixbase, int* f_ix,
                          float* hbase, int* f_h) {
    load_W(Wsm, Wg, 0, true, j, tid);
    int lane = tid & 31, w = tid >> 5, q = w & 3, kh = w >> 2;
    int cu = tid >> 5, cb = tid & 31;          // cell mapping: unit, batch
    float creg = 0.f;                          // cell state in register
    __syncthreads();
    for (int t = 0; t < Tlen; ++t) {
        spin_acq(&f_ix[t], NBS);
        spin_acq(&f_h[t], NBS);
        unsigned long long acc[8];
        gemm2(Wsm, hbase + (size_t)t*HB, lane, q, kh, acc);
        float2 ixr[8];
        if (kh == 0) {
#pragma unroll
            for (int rr = 0; rr < 2; ++rr) {
                int r = lane + rr*32;
                int G = (r >> 4)*Hdim + j*UPB + (r & 15);
                const float2* ip2 = reinterpret_cast<const float2*>(
                    ixbase + ((size_t)t*Gdim + G)*Bsz + q*8);
#pragma unroll
                for (int m = 0; m < 4; ++m) ixr[rr*4 + m] = __ldcg(ip2 + m);
            }
        } else {
            write_partials(part, kh, lane, q, acc);
        }
        __syncthreads();
        if (kh == 0) {
#pragma unroll
            for (int rr = 0; rr < 2; ++rr) {
                int r = lane + rr*32;
                const float* pp = part + r*PPAD + q*8;
                float2* gp = reinterpret_cast<float2*>(gsm + r*GPAD + q*8);
#pragma unroll
                for (int m = 0; m < 4; ++m) {
                    U64F2 u; u.u = acc[rr*4 + m];
                    float2 g;
                    g.x = u.f.x + pp[2*m]   + pp[PSTR + 2*m]   + pp[2*PSTR + 2*m]   + ixr[rr*4+m].x;
                    g.y = u.f.y + pp[2*m+1] + pp[PSTR + 2*m+1] + pp[2*PSTR + 2*m+1] + ixr[rr*4+m].y;
                    gp[m] = g;
                }
            }
        }
        __syncthreads();
        {   // LSTM cell: one (unit,batch) per thread
            float gi = gsm[cu*GPAD + cb];
            float gf = gsm[(UPB   + cu)*GPAD + cb];
            float gg = gsm[(2*UPB + cu)*GPAD + cb];
            float go = gsm[(3*UPB + cu)*GPAD + cb];
            creg = sigf(gf)*creg + sigf(gi)*tanhf(gg);
            float h = sigf(go)*tanhf(creg);
            hbase[(size_t)(t + 1)*HB + (j*UPB + cu)*Bsz + cb] = h;
            __threadfence();
        }
        __syncthreads();
        if (tid == 0) atomicAdd(&f_h[t + 1], 1);
    }
}

// ---------------- kernels --------------------------------------------------
__global__ void reset_kernel() {
    int i = blockIdx.x*256 + threadIdx.x;   // 16384 threads
    if (i < Tlen) { g_f_embT[i] = 0; g_f_ix1[i] = 0; g_f_ix2[i] = 0; }
    if (i <= Tlen) { g_f_h1[i] = (i == 0) ? NBS : 0; g_f_h2[i] = (i == 0) ? NBS : 0; }
    if (i < HB) { g_h1[i] = 0.f; g_h2[i] = 0.f; }
}

__global__ void __launch_bounds__(THR, 1)
lstm_persist(const int* __restrict__ x, const int* __restrict__ labels,
             const float* __restrict__ emb,
             const float* __restrict__ Wih, const float* __restrict__ Whh,
             const float* __restrict__ bih, const float* __restrict__ bhh,
             const float* __restrict__ fcw, const float* __restrict__ fcb,
             float* __restrict__ out, int out_size) {
    extern __shared__ float sm[];
    int bid = blockIdx.x, tid = threadIdx.x;
    float* Wsm  = sm;
    float* part = sm + SM_W;
    float* gsm  = part + SM_PART;

    if (bid < NBA0) {
        // ---- embedding gather + transpose: embT[t][h][b] = emb[x[b][t]][h]
        float* tsm = sm;                       // [b][h] staging, stride 513
        int* rows = reinterpret_cast<int*>(sm + 17000);
        for (int t = bid; t < Tlen; t += NBA0) {
            if (t >= LAG) spin_acq(&g_f_ix1[t - LAG], NBS);
            if (tid < Bsz) rows[tid] = x[tid*Tlen + t];
            __syncthreads();
#pragma unroll
            for (int i = 0; i < 8; ++i) {
                int idx = tid + i*THR;         // 0..4095
                int b = idx >> 7, h4 = idx & 127;
                float4 v = *reinterpret_cast<const float4*>(emb + (size_t)rows[b]*Hdim + h4*4);
                tsm[b*513 + h4*4 + 0] = v.x; tsm[b*513 + h4*4 + 1] = v.y;
                tsm[b*513 + h4*4 + 2] = v.z; tsm[b*513 + h4*4 + 3] = v.w;
            }
            __syncthreads();
            int b = tid & 31, hb = tid >> 5;
#pragma unroll 8
            for (int hh = 0; hh < 32; ++hh) {
                int h = hb*32 + hh;
                g_embT[(size_t)t*HB + h*Bsz + b] = tsm[b*513 + h];
            }
            __threadfence();
            __syncthreads();
            if (tid == 0) atomicAdd(&g_f_embT[t], 1);
        }
        return;
    }

    int role = (bid - NBA0) >> 5;   // 0=ix1, 1=rec1, 2=ix2, 3=rec2
    int j = (bid - NBA0) & 31;

    if (role == 0) {
        stage_ff(j, tid, Wsm, part, Wih, bih, bhh,
                 g_embT, 0, g_f_embT, 1, g_ix1, g_f_ix1, g_f_h1);
    } else if (role == 1) {
        stage_rec(j, tid, Wsm, part, gsm, Whh, g_ix1, g_f_ix1, g_h1, g_f_h1);
    } else if (role == 2) {
        stage_ff(j, tid, Wsm, part, Wih + (size_t)Gdim*Hdim, bih + Gdim, bhh + Gdim,
                 g_h1, 1, g_f_h1, NBS, g_ix2, g_f_ix2, g_f_h2);
    } else {
        stage_rec(j, tid, Wsm, part, gsm, Whh + (size_t)Gdim*Hdim,
                  g_ix2, g_f_ix2, g_h2, g_f_h2);
        if (j == 0) {
            // ---- classifier + log-softmax + NLL on final h2
            spin_acq(&g_f_h2[Tlen], NBS);
            __syncthreads();
            float* ls = gsm;   // reuse smem for logits[32][4]
            if (tid < 128) {
                int n = tid & 3, b = tid >> 2;
                float a = fcb[n];
                const float* wv = fcw + n*Hdim;
                const float* h2 = g_h2 + (size_t)Tlen*HB;
                for (int h = 0; h < Hdim; ++h) a += wv[h]*__ldcg(h2 + h*Bsz + b);
                ls[b*4 + n] = a;
            }
            __syncthreads();
            if (tid == 0) {
                float loss = 0.f;
                for (int b = 0; b < Bsz; ++b) {
                    float l0 = ls[b*4], l1 = ls[b*4+1], l2 = ls[b*4+2], l3 = ls[b*4+3];
                    float m = fmaxf(fmaxf(l0, l1), fmaxf(l2, l3));
                    float s = expf(l0-m) + expf(l1-m) + expf(l2-m) + expf(l3-m);
                    float lse = m + logf(s);
                    loss -= (ls[b*4 + labels[b]] - lse);
                }
                loss /= (float)Bsz;
                if (out_size >= 129) {
                    out[0] = loss;
                    for (int i = 0; i < 128; ++i) out[1 + i] = ls[i];
                    for (int i = 129; i < out_size; ++i) out[i] = 0.f;
                } else if (out_size == 128) {
                    for (int i = 0; i < 128; ++i) out[i] = ls[i];
                } else {
                    out[0] = loss;
                    for (int i = 1; i < out_size; ++i) out[i] = ls[i - 1];
                }
            }
        }
    }
}

// ---------------- launch ---------------------------------------------------
extern "C" void kernel_launch(void* const* d_in, const int* in_sizes, int n_in,
                              void* d_out, int out_size) {
    const int*   x      = (const int*)d_in[0];
    const int*   labels = (const int*)d_in[1];
    const float* emb    = (const float*)d_in[2];
    const float* Wih    = (const float*)d_in[3];
    const float* Whh    = (const float*)d_in[4];
    const float* bih    = (const float*)d_in[5];
    const float* bhh    = (const float*)d_in[6];
    const float* fcw    = (const float*)d_in[7];
    const float* fcb    = (const float*)d_in[8];
    (void)in_sizes; (void)n_in;

    cudaFuncSetAttribute(lstm_persist, cudaFuncAttributeMaxDynamicSharedMemorySize, SMEM_BYTES);
    reset_kernel<<<64, 256>>>();
    lstm_persist<<<NBA0 + 4*NBS, THR, SMEM_BYTES>>>(
        x, labels, emb, Wih, Whh, bih, bhh, fcw, fcb, (float*)d_out, out_size);
}

// round 9
// speedup vs baseline: 1.2838x; 1.2838x over previous
#include <cuda_runtime.h>
#include <math.h>

#define Bsz   32
#define Tlen  2048
#define Hdim  512
#define Gdim  2048
#define HB    (Hdim*Bsz)      // 16384
#define NBS   32              // blocks per GEMM stage
#define NBA0  4               // embedding gather blocks
#define RPB   64              // gate rows per block
#define UPB   16              // hidden units per recurrent block
#define LAG   64              // run-ahead throttle (keeps traffic in L2)
#define THR   512
#define GPAD  34              // gate-exchange row stride
#define PPAD  33              // partial-buffer row stride
#define PSTR  (RPB*PPAD)      // 2112 floats per kh-partial plane

// smem layout (floats)
#define SM_W    (Hdim*RPB)            // 32768 (k-pair interleaved)
#define SM_IN   HB                    // 16384 : 16 warps x 1024-float strips
#define SM_PART (3*PSTR)              // 6336
#define SM_GATE (RPB*GPAD)            // 2176
#define SMEM_FLOATS (SM_W+SM_IN+SM_PART+SM_GATE)   // 57664
#define SMEM_BYTES  (SMEM_FLOATS*4)                // 230656

// ---------------- global scratch ------------------------------------------
static __device__ __align__(16) float g_embT[(size_t)Tlen*HB];
static __device__ __align__(16) float g_ix1[(size_t)Tlen*Gdim*Bsz];
static __device__ __align__(16) float g_ix2[(size_t)Tlen*Gdim*Bsz];
static __device__ __align__(16) float g_h1[(size_t)(Tlen+1)*HB];
static __device__ __align__(16) float g_h2[(size_t)(Tlen+1)*HB];
static __device__ int g_f_embT[Tlen];
static __device__ int g_f_ix1[Tlen];
static __device__ int g_f_ix2[Tlen];
static __device__ int g_f_h1[Tlen+1];
static __device__ int g_f_h2[Tlen+1];

// ---------------- helpers --------------------------------------------------
union U64F2 { unsigned long long u; float2 f; };

__device__ __forceinline__ float sigf(float x) { return 1.0f / (1.0f + expf(-x)); }

__device__ __forceinline__ void spin_acq(const int* p, int v) {
    int x;
    for (;;) {
        asm volatile("ld.acquire.gpu.global.s32 %0, [%1];" : "=r"(x) : "l"(p) : "memory");
        if (x >= v) break;
        __nanosleep(40);
    }
}

__device__ __forceinline__ void flag_release(int* p) {
    asm volatile("red.release.gpu.global.add.s32 [%0], 1;" :: "l"(p) : "memory");
}

// Per-warp private input staging: warp (q,kh) copies its 4KB slice
// in[k in kh*128..+128][b in q*8..+8] into its own smem strip (k-major,
// 8 floats per k). 8 LDG.128 per lane, MLP=8, then 8 STS.128. No block sync.
__device__ __forceinline__ void stage_slice(float* wsm_in, const float* __restrict__ gin,
                                            int lane, int q, int kh) {
    const float* src = gin + kh*128*Bsz + q*8;
    int k0 = lane >> 1, hf = lane & 1;
    float4 v[8];
#pragma unroll
    for (int i = 0; i < 8; ++i)
        v[i] = __ldcg(reinterpret_cast<const float4*>(src + (i*16 + k0)*Bsz + hf*4));
#pragma unroll
    for (int i = 0; i < 8; ++i)
        *reinterpret_cast<float4*>(wsm_in + (i*16 + k0)*8 + hf*4) = v[i];
    __syncwarp();
}

// Stage W slice [64 rows x 512 k] into smem, k-PAIR interleaved:
//   Wsm[(k>>1)*128 + (r&31)*4 + (k&1)*2 + (r>>5)]
__device__ __forceinline__ void load_W(float* Wsm, const float* __restrict__ Wg,
                                       int rowbase, bool strided, int j, int tid) {
    for (int idx = tid; idx < RPB*Hdim; idx += THR) {
        int rl = idx >> 9, k = idx & 511;
        int grow = strided ? ((rl >> 4)*Hdim + j*UPB + (rl & 15)) : (rowbase + rl);
        Wsm[(k >> 1)*128 + (rl & 31)*4 + (k & 1)*2 + (rl >> 5)] =
            Wg[(size_t)grow*Hdim + k];
    }
}

// GEMM over the warp's private smem strip: 64 k-pair iters, 16 FMA2 each.
__device__ __forceinline__ void gemm2(const float* __restrict__ Wsm,
                                      const float* __restrict__ ip,
                                      int lane, int kh,
                                      unsigned long long acc[8]) {
#pragma unroll
    for (int i = 0; i < 8; ++i) acc[i] = 0ull;
    const float4* wp = reinterpret_cast<const float4*>(Wsm) + kh*2048 + lane;
#pragma unroll 8
    for (int p = 0; p < 64; ++p) {
        float4 w = wp[p*32];
        const ulonglong2* i0 = reinterpret_cast<const ulonglong2*>(ip + p*16);
        ulonglong2 v00 = i0[0];
        ulonglong2 v01 = i0[1];   // k+1's 8 floats follow contiguously
        unsigned long long wa, wb, wc, wd;
        asm("mov.b64 %0, {%1, %1};" : "=l"(wa) : "f"(w.x));
        asm("mov.b64 %0, {%1, %1};" : "=l"(wb) : "f"(w.y));
        asm("mov.b64 %0, {%1, %1};" : "=l"(wc) : "f"(w.z));
        asm("mov.b64 %0, {%1, %1};" : "=l"(wd) : "f"(w.w));
        // k = 2p : floats ip[p*16 .. p*16+7]
        asm("fma.rn.f32x2 %0, %1, %2, %0;" : "+l"(acc[0]) : "l"(wa), "l"(v00.x));
        asm("fma.rn.f32x2 %0, %1, %2, %0;" : "+l"(acc[1]) : "l"(wa), "l"(v00.y));
        asm("fma.rn.f32x2 %0, %1, %2, %0;" : "+l"(acc[4]) : "l"(wb), "l"(v00.x));
        asm("fma.rn.f32x2 %0, %1, %2, %0;" : "+l"(acc[5]) : "l"(wb), "l"(v00.y));
        // k = 2p+1 : floats ip[p*16+8 .. p*16+15]
        asm("fma.rn.f32x2 %0, %1, %2, %0;" : "+l"(acc[2]) : "l"(wc), "l"(v01.x));
        asm("fma.rn.f32x2 %0, %1, %2, %0;" : "+l"(acc[3]) : "l"(wc), "l"(v01.y));
        asm("fma.rn.f32x2 %0, %1, %2, %0;" : "+l"(acc[6]) : "l"(wd), "l"(v01.x));
        asm("fma.rn.f32x2 %0, %1, %2, %0;" : "+l"(acc[7]) : "l"(wd), "l"(v01.y));
    }
    // fold the two k-phases: acc[0]+=acc[2], etc.
    U64F2 a, b;
#pragma unroll
    for (int m = 0; m < 2; ++m) {
        a.u = acc[m]; b.u = acc[m+2];
        a.f.x += b.f.x; a.f.y += b.f.y; acc[m] = a.u;
        a.u = acc[m+4]; b.u = acc[m+6];
        a.f.x += b.f.x; a.f.y += b.f.y; acc[m+4] = a.u;
    }
    acc[2] = acc[4]; acc[3] = acc[5];   // compact: rows {lane, lane+32} x 4 f2
}

// After gemm2+compact: acc[0..1] = row lane (b q*8..+3, +4..+7 as f2 pairs)?
// Layout: acc[0],acc[1] = row lane, batches (0,1),(2,3); acc[2],acc[3] = row lane+32.
// NOTE: each f2 covers 2 batches; 4 f2 span 8 batches -> need 4 accs per row.
// We kept 8 accs pre-fold covering (row, khalf, 4 batches f2x2): fold merged
// k-phases, leaving acc[0..3] row lane (4 f2 = 8 batches), acc[4..7] row lane+32.
// (The compact step above is wrong for that; do NOT compact — see gemm2b.)

__device__ __forceinline__ void gemm2b(const float* __restrict__ Wsm,
                                       const float* __restrict__ ip,
                                       int lane, int kh,
                                       unsigned long long acc[8]) {
#pragma unroll
    for (int i = 0; i < 8; ++i) acc[i] = 0ull;
    const float4* wp = reinterpret_cast<const float4*>(Wsm) + kh*2048 + lane;
#pragma unroll 8
    for (int p = 0; p < 64; ++p) {
        float4 w = wp[p*32];
        const ulonglong2* i0 = reinterpret_cast<const ulonglong2*>(ip + p*16);
        ulonglong2 v00 = i0[0];   // k=2p, batches 0-3
        ulonglong2 v01 = i0[1];   // k=2p, batches 4-7
        const ulonglong2* i1 = reinterpret_cast<const ulonglong2*>(ip + p*16 + 8);
        ulonglong2 v10 = i1[0];   // k=2p+1, batches 0-3
        ulonglong2 v11 = i1[1];   // k=2p+1, batches 4-7
        unsigned long long wa, wb, wc, wd;
        asm("mov.b64 %0, {%1, %1};" : "=l"(wa) : "f"(w.x));  // row lane,   k=2p
        asm("mov.b64 %0, {%1, %1};" : "=l"(wb) : "f"(w.y));  // row lane+32,k=2p
        asm("mov.b64 %0, {%1, %1};" : "=l"(wc) : "f"(w.z));  // row lane,   k=2p+1
        asm("mov.b64 %0, {%1, %1};" : "=l"(wd) : "f"(w.w));  // row lane+32,k=2p+1
        asm("fma.rn.f32x2 %0, %1, %2, %0;" : "+l"(acc[0]) : "l"(wa), "l"(v00.x));
        asm("fma.rn.f32x2 %0, %1, %2, %0;" : "+l"(acc[1]) : "l"(wa), "l"(v00.y));
        asm("fma.rn.f32x2 %0, %1, %2, %0;" : "+l"(acc[2]) : "l"(wa), "l"(v01.x));
        asm("fma.rn.f32x2 %0, %1, %2, %0;" : "+l"(acc[3]) : "l"(wa), "l"(v01.y));
        asm("fma.rn.f32x2 %0, %1, %2, %0;" : "+l"(acc[4]) : "l"(wb), "l"(v00.x));
        asm("fma.rn.f32x2 %0, %1, %2, %0;" : "+l"(acc[5]) : "l"(wb), "l"(v00.y));
        asm("fma.rn.f32x2 %0, %1, %2, %0;" : "+l"(acc[6]) : "l"(wb), "l"(v01.x));
        asm("fma.rn.f32x2 %0, %1, %2, %0;" : "+l"(acc[7]) : "l"(wb), "l"(v01.y));
        asm("fma.rn.f32x2 %0, %1, %2, %0;" : "+l"(acc[0]) : "l"(wc), "l"(v10.x));
        asm("fma.rn.f32x2 %0, %1, %2, %0;" : "+l"(acc[1]) : "l"(wc), "l"(v10.y));
        asm("fma.rn.f32x2 %0, %1, %2, %0;" : "+l"(acc[2]) : "l"(wc), "l"(v11.x));
        asm("fma.rn.f32x2 %0, %1, %2, %0;" : "+l"(acc[3]) : "l"(wc), "l"(v11.y));
        asm("fma.rn.f32x2 %0, %1, %2, %0;" : "+l"(acc[4]) : "l"(wd), "l"(v10.x));
        asm("fma.rn.f32x2 %0, %1, %2, %0;" : "+l"(acc[5]) : "l"(wd), "l"(v10.y));
        asm("fma.rn.f32x2 %0, %1, %2, %0;" : "+l"(acc[6]) : "l"(wd), "l"(v11.x));
        asm("fma.rn.f32x2 %0, %1, %2, %0;" : "+l"(acc[7]) : "l"(wd), "l"(v11.y));
    }
}

__device__ __forceinline__ void write_partials(float* part, int kh, int lane, int q,
                                               const unsigned long long acc[8]) {
#pragma unroll
    for (int rr = 0; rr < 2; ++rr) {
        float* pp = part + (kh-1)*PSTR + (lane + rr*32)*PPAD + q*8;
#pragma unroll
        for (int m = 0; m < 4; ++m) {
            U64F2 u; u.u = acc[rr*4 + m];
            pp[2*m] = u.f.x; pp[2*m + 1] = u.f.y;
        }
    }
}

// ---------------- pipeline stages -----------------------------------------
__device__ void stage_ff(int j, int tid, float* Wsm, float* insm, float* part,
                         const float* Wg, const float* biasA, const float* biasB,
                         const float* inbase, int slot_off, int* f_in, int in_thresh,
                         float* outbase, int* f_out, int* f_throttle) {
    load_W(Wsm, Wg, j*RPB, false, j, tid);
    int lane = tid & 31, w = tid >> 5, q = w & 3, kh = w >> 2;
    float* myin = insm + w*1024;
    float bias0 = biasA[j*RPB + lane]      + biasB[j*RPB + lane];
    float bias1 = biasA[j*RPB + lane + 32] + biasB[j*RPB + lane + 32];
    __syncthreads();
    for (int t = 0; t < Tlen; ++t) {
        spin_acq(&f_in[t + slot_off], in_thresh);
        if (t >= LAG) spin_acq(&f_throttle[t - LAG], NBS);
        stage_slice(myin, inbase + (size_t)(t + slot_off)*HB, lane, q, kh);
        unsigned long long acc[8];
        gemm2b(Wsm, myin, lane, kh, acc);
        if (kh > 0) write_partials(part, kh, lane, q, acc);
        __syncthreads();
        if (kh == 0) {
#pragma unroll
            for (int rr = 0; rr < 2; ++rr) {
                int r = lane + rr*32;
                float bias = rr ? bias1 : bias0;
                const float* pp = part + r*PPAD + q*8;
                float2* op = reinterpret_cast<float2*>(
                    outbase + ((size_t)t*Gdim + j*RPB + r)*Bsz + q*8);
#pragma unroll
                for (int m = 0; m < 4; ++m) {
                    U64F2 u; u.u = acc[rr*4 + m];
                    float2 g;
                    g.x = u.f.x + pp[2*m]   + pp[PSTR + 2*m]   + pp[2*PSTR + 2*m]   + bias;
                    g.y = u.f.y + pp[2*m+1] + pp[PSTR + 2*m+1] + pp[2*PSTR + 2*m+1] + bias;
                    op[m] = g;
                }
            }
        }
        __syncthreads();
        if (tid == 0) flag_release(&f_out[t]);
    }
}

__device__ void stage_rec(int j, int tid, float* Wsm, float* insm, float* part, float* gsm,
                          const float* Wg, const float* ixbase, int* f_ix,
                          float* hbase, int* f_h) {
    load_W(Wsm, Wg, 0, true, j, tid);
    int lane = tid & 31, w = tid >> 5, q = w & 3, kh = w >> 2;
    float* myin = insm + w*1024;
    int cu = tid >> 5, cb = tid & 31;
    float creg = 0.f;
    __syncthreads();
    for (int t = 0; t < Tlen; ++t) {
        float2 ixr[8];
        if (kh == 0) {
            spin_acq(&f_ix[t], NBS);
            // prefetch ix before the GEMM so its L2 latency hides under FMAs
#pragma unroll
            for (int rr = 0; rr < 2; ++rr) {
                int r = lane + rr*32;
                int G = (r >> 4)*Hdim + j*UPB + (r & 15);
                const float2* ip2 = reinterpret_cast<const float2*>(
                    ixbase + ((size_t)t*Gdim + G)*Bsz + q*8);
#pragma unroll
                for (int m = 0; m < 4; ++m) ixr[rr*4 + m] = __ldcg(ip2 + m);
            }
        }
        spin_acq(&f_h[t], NBS);
        stage_slice(myin, hbase + (size_t)t*HB, lane, q, kh);
        unsigned long long acc[8];
        gemm2b(Wsm, myin, lane, kh, acc);
        if (kh > 0) write_partials(part, kh, lane, q, acc);
        __syncthreads();
        if (kh == 0) {
#pragma unroll
            for (int rr = 0; rr < 2; ++rr) {
                int r = lane + rr*32;
                const float* pp = part + r*PPAD + q*8;
                float2* gp = reinterpret_cast<float2*>(gsm + r*GPAD + q*8);
#pragma unroll
                for (int m = 0; m < 4; ++m) {
                    U64F2 u; u.u = acc[rr*4 + m];
                    float2 g;
                    g.x = u.f.x + pp[2*m]   + pp[PSTR + 2*m]   + pp[2*PSTR + 2*m]   + ixr[rr*4+m].x;
                    g.y = u.f.y + pp[2*m+1] + pp[PSTR + 2*m+1] + pp[2*PSTR + 2*m+1] + ixr[rr*4+m].y;
                    gp[m] = g;
                }
            }
        }
        __syncthreads();
        {   // LSTM cell: one (unit,batch) per thread
            float gi = gsm[cu*GPAD + cb];
            float gf = gsm[(UPB   + cu)*GPAD + cb];
            float gg = gsm[(2*UPB + cu)*GPAD + cb];
            float go = gsm[(3*UPB + cu)*GPAD + cb];
            creg = sigf(gf)*creg + sigf(gi)*tanhf(gg);
            float h = sigf(go)*tanhf(creg);
            hbase[(size_t)(t + 1)*HB + (j*UPB + cu)*Bsz + cb] = h;
        }
        __syncthreads();
        if (tid == 0) flag_release(&f_h[t + 1]);
    }
}

// ---------------- kernels --------------------------------------------------
__global__ void reset_kernel() {
    int i = blockIdx.x*256 + threadIdx.x;
    if (i < Tlen) { g_f_embT[i] = 0; g_f_ix1[i] = 0; g_f_ix2[i] = 0; }
    if (i <= Tlen) { g_f_h1[i] = (i == 0) ? NBS : 0; g_f_h2[i] = (i == 0) ? NBS : 0; }
    if (i < HB) { g_h1[i] = 0.f; g_h2[i] = 0.f; }
}

__global__ void __launch_bounds__(THR, 1)
lstm_persist(const int* __restrict__ x, const int* __restrict__ labels,
             const float* __restrict__ emb,
             const float* __restrict__ Wih, const float* __restrict__ Whh,
             const float* __restrict__ bih, const float* __restrict__ bhh,
             const float* __restrict__ fcw, const float* __restrict__ fcb,
             float* __restrict__ out, int out_size) {
    extern __shared__ float sm[];
    int bid = blockIdx.x, tid = threadIdx.x;
    float* Wsm  = sm;
    float* insm = sm + SM_W;
    float* part = insm + SM_IN;
    float* gsm  = part + SM_PART;

    if (bid < NBA0) {
        float* tsm = sm;                       // [b][h] staging, stride 513
        int* rows = reinterpret_cast<int*>(sm + 17000);
        for (int t = bid; t < Tlen; t += NBA0) {
            if (t >= LAG) spin_acq(&g_f_ix1[t - LAG], NBS);
            if (tid < Bsz) rows[tid] = x[tid*Tlen + t];
            __syncthreads();
#pragma unroll
            for (int i = 0; i < 8; ++i) {
                int idx = tid + i*THR;
                int b = idx >> 7, h4 = idx & 127;
                float4 v = *reinterpret_cast<const float4*>(emb + (size_t)rows[b]*Hdim + h4*4);
                tsm[b*513 + h4*4 + 0] = v.x; tsm[b*513 + h4*4 + 1] = v.y;
                tsm[b*513 + h4*4 + 2] = v.z; tsm[b*513 + h4*4 + 3] = v.w;
            }
            __syncthreads();
            int b = tid & 31, hb = tid >> 5;
#pragma unroll 8
            for (int hh = 0; hh < 32; ++hh) {
                int h = hb*32 + hh;
                g_embT[(size_t)t*HB + h*Bsz + b] = tsm[b*513 + h];
            }
            __syncthreads();
            if (tid == 0) flag_release(&g_f_embT[t]);
        }
        return;
    }

    int role = (bid - NBA0) >> 5;
    int j = (bid - NBA0) & 31;

    if (role == 0) {
        stage_ff(j, tid, Wsm, insm, part, Wih, bih, bhh,
                 g_embT, 0, g_f_embT, 1, g_ix1, g_f_ix1, g_f_h1);
    } else if (role == 1) {
        stage_rec(j, tid, Wsm, insm, part, gsm, Whh, g_ix1, g_f_ix1, g_h1, g_f_h1);
    } else if (role == 2) {
        stage_ff(j, tid, Wsm, insm, part, Wih + (size_t)Gdim*Hdim, bih + Gdim, bhh + Gdim,
                 g_h1, 1, g_f_h1, NBS, g_ix2, g_f_ix2, g_f_h2);
    } else {
        stage_rec(j, tid, Wsm, insm, part, gsm, Whh + (size_t)Gdim*Hdim,
                  g_ix2, g_f_ix2, g_h2, g_f_h2);
        if (j == 0) {
            spin_acq(&g_f_h2[Tlen], NBS);
            __syncthreads();
            float* ls = gsm;
            if (tid < 128) {
                int n = tid & 3, b = tid >> 2;
                float a = fcb[n];
                const float* wv = fcw + n*Hdim;
                const float* h2 = g_h2 + (size_t)Tlen*HB;
                for (int h = 0; h < Hdim; ++h) a += wv[h]*__ldcg(h2 + h*Bsz + b);
                ls[b*4 + n] = a;
            }
            __syncthreads();
            if (tid == 0) {
                float loss = 0.f;
                for (int b = 0; b < Bsz; ++b) {
                    float l0 = ls[b*4], l1 = ls[b*4+1], l2 = ls[b*4+2], l3 = ls[b*4+3];
                    float m = fmaxf(fmaxf(l0, l1), fmaxf(l2, l3));
                    float s = expf(l0-m) + expf(l1-m) + expf(l2-m) + expf(l3-m);
                    float lse = m + logf(s);
                    loss -= (ls[b*4 + labels[b]] - lse);
                }
                loss /= (float)Bsz;
                if (out_size >= 129) {
                    out[0] = loss;
                    for (int i = 0; i < 128; ++i) out[1 + i] = ls[i];
                    for (int i = 129; i < out_size; ++i) out[i] = 0.f;
                } else if (out_size == 128) {
                    for (int i = 0; i < 128; ++i) out[i] = ls[i];
                } else {
                    out[0] = loss;
                    for (int i = 1; i < out_size; ++i) out[i] = ls[i - 1];
                }
            }
        }
    }
}

// ---------------- launch ---------------------------------------------------
extern "C" void kernel_launch(void* const* d_in, const int* in_sizes, int n_in,
                              void* d_out, int out_size) {
    const int*   x      = (const int*)d_in[0];
    const int*   labels = (const int*)d_in[1];
    const float* emb    = (const float*)d_in[2];
    const float* Wih    = (const float*)d_in[3];
    const float* Whh    = (const float*)d_in[4];
    const float* bih    = (const float*)d_in[5];
    const float* bhh    = (const float*)d_in[6];
    const float* fcw    = (const float*)d_in[7];
    const float* fcb    = (const float*)d_in[8];
    (void)in_sizes; (void)n_in;

    cudaFuncSetAttribute(lstm_persist, cudaFuncAttributeMaxDynamicSharedMemorySize, SMEM_BYTES);
    reset_kernel<<<64, 256>>>();
    lstm_persist<<<NBA0 + 4*NBS, THR, SMEM_BYTES>>>(
        x, labels, emb, Wih, Whh, bih, bhh, fcw, fcb, (float*)d_out, out_size);
}